// round 4
// baseline (speedup 1.0000x reference)
#include <cuda_runtime.h>
#include <cstdint>

// Problem constants
#define B   128
#define T   1024
#define H   512
#define G   2048   // 4*H gate columns
#define V   256
#define NBLK 128   // 32 h-unit groups x 4 batch groups
#define NTHR 512   // 16 warps: 2 k-halves x (2 batch-groups x 4 g-groups)
#define BT   32    // batch tile per block
#define GC   64    // gate cols per block (16 h-units x 4 gates)

// Shared memory carve (bytes)
#define WS_BYTES (256*64*8)   // Ws2: [256 k2][64 g] float2   = 131072
#define HS_BYTES (256*32*8)   // Hs2: [256 k2][32 b] float2   =  65536
#define GS_STRIDE 68
#define GS_BYTES (2*32*GS_STRIDE*4)  // two partial gate buffers = 17408
#define SMEM_BYTES (WS_BYTES + HS_BYTES + GS_BYTES + 128 + 128)

// Device-global scratch (allocation-free per harness rules)
__device__ float     g_WihT[V*G];              // W_ih^T with biases folded: [v][g]
__device__ float2    g_hbuf[2][(H/2)*B];       // double-buffered h, k-pair interleaved: [k2][b]
__device__ unsigned  g_bar;

__device__ __forceinline__ void fma2(unsigned long long &d, unsigned long long a, unsigned long long b) {
    asm volatile("fma.rn.f32x2 %0, %1, %2, %0;" : "+l"(d) : "l"(a), "l"(b));
}
__device__ __forceinline__ float2 u2f(unsigned long long v) {
    float2 r; asm("mov.b64 {%0, %1}, %2;" : "=f"(r.x), "=f"(r.y) : "l"(v)); return r;
}
__device__ __forceinline__ float sigf(float x) { return 1.0f / (1.0f + expf(-x)); }

// Per-launch init: reset barrier, zero h0 buffer, build projection table
// projT[v][g] = W_ih[g][v] + b_ih[g] + b_hh[g]
__global__ void init_kernel(const float* __restrict__ W_ih,
                            const float* __restrict__ b_ih,
                            const float* __restrict__ b_hh) {
    int idx = blockIdx.x * blockDim.x + threadIdx.x;
    int stride = gridDim.x * blockDim.x;
    if (idx == 0) g_bar = 0u;
    for (int i = idx; i < V*G; i += stride) {
        int v = i >> 11;           // /G
        int g = i & (G - 1);
        g_WihT[i] = W_ih[g*V + v] + b_ih[g] + b_hh[g];
    }
    for (int i = idx; i < (H/2)*B; i += stride) g_hbuf[0][i] = make_float2(0.f, 0.f);
}

extern __shared__ char smem_raw[];

__global__ __launch_bounds__(NTHR, 1)
void lstm_persistent(const int* __restrict__ x, const int* __restrict__ x_len,
                     const float* __restrict__ W_hh, float* __restrict__ out) {
    float2* Ws2 = (float2*)smem_raw;                       // [256][64] k-pair packed W slice
    float2* Hs2 = (float2*)(smem_raw + WS_BYTES);          // [256][32] k-pair packed h tile
    float*  Gs  = (float*)(smem_raw + WS_BYTES + HS_BYTES);// [2][32][68] partial gates
    int*   vbuf = (int*)(Gs + 2*32*GS_STRIDE);             // [32] token ids this step
    int*   xls  = vbuf + 32;                               // [32] x_len cache

    const int tid  = threadIdx.x;
    const int hug  = blockIdx.x & 31;   // h-unit group
    const int bg   = blockIdx.x >> 5;   // batch group
    const int hu0  = hug * 16;
    const int b0   = bg * BT;

    // Warp grid: 2 k-halves x 2 batch-groups x 4 gate-col-groups
    const int warp = tid >> 5;
    const int lane = tid & 31;
    const int wk = warp >> 3;           // k-half: k2 in [wk*128, wk*128+128)
    const int w8 = warp & 7;
    const int wb = w8 & 1;              // batch-group of warp (16 rows)
    const int wg = w8 >> 1;             // g-group of warp (16 cols == one gate type)
    const int bl = lane >> 2;           // 0..7  -> 2 batch rows each
    const int gl = lane & 3;            // 0..3  -> 4 gate cols each
    const int bB = wb*16 + bl*2;        // this lane's batch base (2 rows)
    const int gB = wg*16 + gl*4;        // this lane's gate-col base (4 cols)

    // ---- Prologue: load W_hh slice (resident all 1024 steps), x_len cache ----
    for (int i = tid; i < GC*256; i += NTHR) {
        int k2 = i >> 6, c = i & 63;
        int grow = ((c >> 4) << 9) + hu0 + (c & 15);   // gate_type*512 + hu0 + u
        Ws2[k2*64 + c] = *(const float2*)&W_hh[grow*H + 2*k2];
    }
    if (tid < BT) xls[tid] = x_len[b0 + tid];

    // Pointwise mapping (threads 0..255 only; c lives in their registers)
    const int u2 = (tid >> 5) & 7;  // 0..7 (h-unit pair index) for tid<256
    const int pb = tid & 31;        // batch row
    float2 creg = make_float2(0.f, 0.f);

    // projection gather base (4 consecutive gate rows per lane -> float4)
    const int prow = wg*512 + hu0 + gl*4;

    // Per-warp GEMM operand bases (k-half offset baked in)
    float* GsMine = Gs + wk*32*GS_STRIDE;

    for (int t = 0; t < T; ++t) {
        // ---- Fill Hs2 from global h (double-buffered) ----
        {
            const float4* src = (const float4*)(g_hbuf[t & 1]);
            float4* dst = (float4*)Hs2;
            #pragma unroll
            for (int i = tid; i < 4096; i += NTHR) {
                int k2 = i >> 4, q = i & 15;
                dst[k2*16 + q] = src[k2*64 + (b0 >> 1) + q];
            }
        }
        if (tid < BT) vbuf[tid] = x[(b0 + tid)*T + t];
        __syncthreads();

        // ---- Prefetch projection (only k-half 0 adds it) ----
        float4 proj[2];
        if (wk == 0) {
            #pragma unroll
            for (int bb = 0; bb < 2; ++bb) {
                int vb = vbuf[bB + bb];
                proj[bb] = *(const float4*)&g_WihT[vb*G + prow];
            }
        } else {
            proj[0] = make_float4(0.f,0.f,0.f,0.f);
            proj[1] = make_float4(0.f,0.f,0.f,0.f);
        }

        // ---- GEMM half: gates[2b x 4g] per lane over 128 k2 ----
        unsigned long long acc[2][4];
        #pragma unroll
        for (int a = 0; a < 4; ++a) { acc[0][a] = 0ull; acc[1][a] = 0ull; }
        const char* hp = (const char*)(Hs2 + wk*128*32 + bB);
        const char* wp = (const char*)(Ws2 + wk*128*64 + gB);
        #pragma unroll 8
        for (int k2 = 0; k2 < 128; ++k2) {
            ulonglong2 hv  = *(const ulonglong2*)hp;          // h for b, b+1
            ulonglong2 w01 = *(const ulonglong2*)wp;          // g0, g1
            ulonglong2 w23 = *(const ulonglong2*)(wp + 16);   // g2, g3
            fma2(acc[0][0], hv.x, w01.x); fma2(acc[0][1], hv.x, w01.y);
            fma2(acc[0][2], hv.x, w23.x); fma2(acc[0][3], hv.x, w23.y);
            fma2(acc[1][0], hv.y, w01.x); fma2(acc[1][1], hv.y, w01.y);
            fma2(acc[1][2], hv.y, w23.x); fma2(acc[1][3], hv.y, w23.y);
            hp += 32*8; wp += 64*8;
        }

        // ---- Reduce k-pairs + add proj, stage partial gates ----
        #pragma unroll
        for (int bb = 0; bb < 2; ++bb) {
            int b = bB + bb;
            float2 a0 = u2f(acc[bb][0]);
            float2 a1 = u2f(acc[bb][1]);
            float2 a2 = u2f(acc[bb][2]);
            float2 a3 = u2f(acc[bb][3]);
            float4 v;
            v.x = a0.x + a0.y + proj[bb].x;
            v.y = a1.x + a1.y + proj[bb].y;
            v.z = a2.x + a2.y + proj[bb].z;
            v.w = a3.x + a3.y + proj[bb].w;
            *(float4*)&GsMine[b*GS_STRIDE + gB] = v;
        }
        __syncthreads();

        // ---- Pointwise LSTM cell (threads 0..255; 2 h-units each) ----
        if (tid < 256) {
            int b = pb;
            int base = b*GS_STRIDE + 2*u2;
            const float* G0 = Gs;
            const float* G1 = Gs + 32*GS_STRIDE;
            float2 i0 = *(float2*)&G0[base];      float2 i1 = *(float2*)&G1[base];
            float2 f0 = *(float2*)&G0[base + 16]; float2 f1 = *(float2*)&G1[base + 16];
            float2 g0 = *(float2*)&G0[base + 32]; float2 g1 = *(float2*)&G1[base + 32];
            float2 o0 = *(float2*)&G0[base + 48]; float2 o1 = *(float2*)&G1[base + 48];
            float2 iv = make_float2(i0.x + i1.x, i0.y + i1.y);
            float2 fv = make_float2(f0.x + f1.x, f0.y + f1.y);
            float2 gv = make_float2(g0.x + g1.x, g0.y + g1.y);
            float2 ov = make_float2(o0.x + o1.x, o0.y + o1.y);
            float2 hprev = Hs2[((hu0 >> 1) + u2)*32 + b];

            float ia = sigf(iv.x), ib = sigf(iv.y);
            float fa = sigf(fv.x), fb = sigf(fv.y);
            float ga = tanhf(gv.x), gb = tanhf(gv.y);
            float oa = sigf(ov.x), ob = sigf(ov.y);
            float ca = fa*creg.x + ia*ga;
            float cb = fb*creg.y + ib*gb;
            float ha = oa*tanhf(ca);
            float hb = ob*tanhf(cb);

            bool m = (t < xls[b]);
            float hca = m ? ha : hprev.x;
            float hcb = m ? hb : hprev.y;
            if (m) { creg.x = ca; creg.y = cb; }

            // carried h -> next-step buffer (coalesced 256B per warp)
            g_hbuf[(t + 1) & 1][((hu0 >> 1) + u2)*B + b0 + b] = make_float2(hca, hcb);

            // sequence output
            float2 outv = m ? make_float2(ha, hb) : make_float2(0.f, 0.f);
            size_t obase = ((size_t)(b0 + b)*T + t)*H + hu0 + 2*u2;
            *(float2*)&out[obase] = outv;

            if (t == T - 1) {
                size_t hoff = (size_t)B*T*H + (size_t)(b0 + b)*H + hu0 + 2*u2;
                *(float2*)&out[hoff] = make_float2(hca, hcb);
                *(float2*)&out[hoff + (size_t)B*H] = creg;
            }
        }

        // ---- Grid barrier (all 128 blocks co-resident by construction) ----
        if (t + 1 < T) {
            __syncthreads();
            if (tid == 0) {
                __threadfence();
                atomicAdd(&g_bar, 1u);
                unsigned target = (unsigned)NBLK * (unsigned)(t + 1);
                while (*((volatile unsigned*)&g_bar) < target) { }
                __threadfence();
            }
            __syncthreads();
        }
    }
}

extern "C" void kernel_launch(void* const* d_in, const int* in_sizes, int n_in,
                              void* d_out, int out_size) {
    const int*   x     = (const int*)d_in[0];
    const int*   x_len = (const int*)d_in[1];
    const float* W_ih  = (const float*)d_in[2];
    const float* W_hh  = (const float*)d_in[3];
    const float* b_ih  = (const float*)d_in[4];
    const float* b_hh  = (const float*)d_in[5];
    float* out = (float*)d_out;

    cudaFuncSetAttribute(lstm_persistent,
                         cudaFuncAttributeMaxDynamicSharedMemorySize, SMEM_BYTES);

    init_kernel<<<256, 256>>>(W_ih, b_ih, b_hh);
    lstm_persistent<<<NBLK, NTHR, SMEM_BYTES>>>(x, x_len, W_hh, out);
}

// round 5
// speedup vs baseline: 1.3429x; 1.3429x over previous
#include <cuda_runtime.h>
#include <cstdint>

// Problem constants
#define B   128
#define T   1024
#define H   512
#define G   2048   // 4*H gate columns
#define V   256
#define NBLK 128   // 32 h-unit groups x 4 batch groups
#define NTHR 256   // 8 warps: 2 b-halves x 4 g-quarters, octet-k interleave inside warp
#define BT   32    // batch tile per block
#define GC   64    // gate cols per block (16 h-units x 4 gates)

// Padded smem strides (float2 units per k2 row) -> bank step 4 per k2: conflict-free
#define WST 66     // Ws2: [256][66] float2  (64 used)
#define HST 34     // Hs2: [256][34] float2  (32 used)
#define GST 68     // gates staging stride (floats)

#define WS_BYTES (256*WST*8)   // 135168
#define HS_BYTES (256*HST*8)   //  69632
#define GS_BYTES (32*GST*4)    //   8704
#define SMEM_BYTES (WS_BYTES + HS_BYTES + GS_BYTES + 256)  // 213760

// Device-global scratch (allocation-free per harness rules)
__device__ float     g_WihT[V*G];              // W_ih^T with biases folded: [v][g]
__device__ float2    g_hbuf[2][(H/2)*B];       // double-buffered h, k-pair interleaved: [k2][b]
__device__ unsigned  g_bar;

__device__ __forceinline__ void fma2(unsigned long long &d, unsigned long long a, unsigned long long b) {
    asm volatile("fma.rn.f32x2 %0, %1, %2, %0;" : "+l"(d) : "l"(a), "l"(b));
}
__device__ __forceinline__ float2 u2f(unsigned long long v) {
    float2 r; asm("mov.b64 {%0, %1}, %2;" : "=f"(r.x), "=f"(r.y) : "l"(v)); return r;
}
__device__ __forceinline__ float sigf(float x) { return 1.0f / (1.0f + expf(-x)); }

// Per-launch init: reset barrier, zero h0, build projection table
// projT[v][g] = W_ih[g][v] + b_ih[g] + b_hh[g]
__global__ void init_kernel(const float* __restrict__ W_ih,
                            const float* __restrict__ b_ih,
                            const float* __restrict__ b_hh) {
    int idx = blockIdx.x * blockDim.x + threadIdx.x;
    int stride = gridDim.x * blockDim.x;
    if (idx == 0) g_bar = 0u;
    for (int i = idx; i < V*G; i += stride) {
        int v = i >> 11;
        int g = i & (G - 1);
        g_WihT[i] = W_ih[g*V + v] + b_ih[g] + b_hh[g];
    }
    for (int i = idx; i < (H/2)*B; i += stride) g_hbuf[0][i] = make_float2(0.f, 0.f);
}

extern __shared__ char smem_raw[];

__global__ __launch_bounds__(NTHR, 1)
void lstm_persistent(const int* __restrict__ x, const int* __restrict__ x_len,
                     const float* __restrict__ W_hh, float* __restrict__ out) {
    float2* Ws2 = (float2*)smem_raw;                       // [256][WST] k-pair packed W slice
    float2* Hs2 = (float2*)(smem_raw + WS_BYTES);          // [256][HST] k-pair packed h tile
    float*  Gs  = (float*)(smem_raw + WS_BYTES + HS_BYTES);// [32][GST] gates
    int*   vbuf = (int*)(Gs + 32*GST);                     // [32] token ids this step
    int*   xls  = vbuf + 32;                               // [32] x_len cache

    const int tid  = threadIdx.x;
    const int hug  = blockIdx.x & 31;   // h-unit group
    const int bg   = blockIdx.x >> 5;   // batch group
    const int hu0  = hug * 16;
    const int b0   = bg * BT;

    // Warp grid: warp = (wb2 b-half, wg4 g-quarter); inside warp:
    //   octet = (bq, gq) 8b x 8g subtile, lanes within octet = k2 phase (ksub)
    const int warp = tid >> 5;
    const int lane = tid & 31;
    const int wb2 = warp & 1;
    const int wg4 = warp >> 1;
    const int oct  = lane >> 3;
    const int ksub = lane & 7;
    const int bq = oct & 1;
    const int gq = oct >> 1;
    const int bB = wb2*16 + bq*8;       // 8 batch rows
    const int gB = wg4*16 + gq*8;       // 8 gate cols (local)

    // ---- Prologue: load W_hh slice (resident all 1024 steps), x_len cache ----
    for (int i = tid; i < GC*256; i += NTHR) {
        int k2 = i >> 6, c = i & 63;
        int grow = ((c >> 4) << 9) + hu0 + (c & 15);   // gate_type*512 + hu0 + u
        Ws2[k2*WST + c] = *(const float2*)&W_hh[grow*H + 2*k2];
    }
    if (tid < BT) xls[tid] = x_len[b0 + tid];

    // Pointwise mapping (all 256 threads; c lives in registers)
    const int u2 = tid >> 5;   // 0..7 (h-unit pair index)
    const int pb = tid & 31;   // batch row
    float2 creg = make_float2(0.f, 0.f);

    // Projection gather row base for this lane's store row (bi == ksub):
    // global gate row for local col gB+j = wg4*512 + hu0 + gq*8 + j
    const int prow = wg4*512 + hu0 + gq*8;

    for (int t = 0; t < T; ++t) {
        // ---- Fill Hs2 from global h (double-buffered), stride HST ----
        {
            const float4* src = (const float4*)(g_hbuf[t & 1]);
            float4* dst = (float4*)Hs2;   // 17 float4 per k2 row
            #pragma unroll
            for (int i = tid; i < 4096; i += NTHR) {
                int k2 = i >> 4, q = i & 15;
                dst[k2*17 + q] = src[k2*64 + (b0 >> 1) + q];
            }
        }
        if (tid < BT) vbuf[tid] = x[(b0 + tid)*T + t];
        __syncthreads();

        // ---- Prefetch projection for this lane's output row (hidden under GEMM) ----
        int vb = vbuf[bB + ksub];
        const float* pr = &g_WihT[vb*G + prow];
        float4 proj0 = *(const float4*)pr;
        float4 proj1 = *(const float4*)(pr + 4);

        // ---- GEMM: 8b x 8g per lane, lane-private k2 = 8j + ksub ----
        unsigned long long acc[8][8];
        #pragma unroll
        for (int b = 0; b < 8; ++b)
            #pragma unroll
            for (int g = 0; g < 8; ++g) acc[b][g] = 0ull;

        const char* hp = (const char*)(Hs2 + ksub*HST + bB);
        const char* wp = (const char*)(Ws2 + ksub*WST + gB);
        #pragma unroll 2
        for (int j = 0; j < 32; ++j) {
            ulonglong2 hv0 = *(const ulonglong2*)hp;
            ulonglong2 hv1 = *(const ulonglong2*)(hp + 16);
            ulonglong2 hv2 = *(const ulonglong2*)(hp + 32);
            ulonglong2 hv3 = *(const ulonglong2*)(hp + 48);
            ulonglong2 wv0 = *(const ulonglong2*)wp;
            ulonglong2 wv1 = *(const ulonglong2*)(wp + 16);
            ulonglong2 wv2 = *(const ulonglong2*)(wp + 32);
            ulonglong2 wv3 = *(const ulonglong2*)(wp + 48);
            unsigned long long h8[8] = {hv0.x, hv0.y, hv1.x, hv1.y, hv2.x, hv2.y, hv3.x, hv3.y};
            unsigned long long w8[8] = {wv0.x, wv0.y, wv1.x, wv1.y, wv2.x, wv2.y, wv3.x, wv3.y};
            #pragma unroll
            for (int b = 0; b < 8; ++b)
                #pragma unroll
                for (int g = 0; g < 8; ++g)
                    fma2(acc[b][g], h8[b], w8[g]);
            hp += 8*HST*8;
            wp += 8*WST*8;
        }

        // ---- k-pair + octet-butterfly reduction, add proj, stage to Gs ----
        #pragma unroll
        for (int bi = 0; bi < 8; ++bi) {
            float s[8];
            #pragma unroll
            for (int gi = 0; gi < 8; ++gi) {
                float2 a = u2f(acc[bi][gi]);
                float v = a.x + a.y;
                v += __shfl_xor_sync(0xffffffffu, v, 1);
                v += __shfl_xor_sync(0xffffffffu, v, 2);
                v += __shfl_xor_sync(0xffffffffu, v, 4);
                s[gi] = v;
            }
            if (ksub == bi) {
                float4 v0 = make_float4(s[0] + proj0.x, s[1] + proj0.y,
                                        s[2] + proj0.z, s[3] + proj0.w);
                float4 v1 = make_float4(s[4] + proj1.x, s[5] + proj1.y,
                                        s[6] + proj1.z, s[7] + proj1.w);
                float* row = &Gs[(bB + bi)*GST + gB];
                *(float4*)row = v0;
                *(float4*)(row + 4) = v1;
            }
        }
        __syncthreads();

        // ---- Pointwise LSTM cell (2 h-units per thread, c in registers) ----
        {
            int b = pb;
            int base = b*GST + 2*u2;
            float2 iv = *(float2*)&Gs[base];
            float2 fv = *(float2*)&Gs[base + 16];
            float2 gv = *(float2*)&Gs[base + 32];
            float2 ov = *(float2*)&Gs[base + 48];
            float2 hprev = Hs2[((hu0 >> 1) + u2)*HST + b];

            float ia = sigf(iv.x), ib = sigf(iv.y);
            float fa = sigf(fv.x), fb = sigf(fv.y);
            float ga = tanhf(gv.x), gb = tanhf(gv.y);
            float oa = sigf(ov.x), ob = sigf(ov.y);
            float ca = fa*creg.x + ia*ga;
            float cb = fb*creg.y + ib*gb;
            float ha = oa*tanhf(ca);
            float hb = ob*tanhf(cb);

            bool m = (t < xls[b]);
            float hca = m ? ha : hprev.x;
            float hcb = m ? hb : hprev.y;
            if (m) { creg.x = ca; creg.y = cb; }

            // carried h -> next-step buffer (coalesced 256B per warp)
            g_hbuf[(t + 1) & 1][((hu0 >> 1) + u2)*B + b0 + b] = make_float2(hca, hcb);

            // sequence output
            float2 outv = m ? make_float2(ha, hb) : make_float2(0.f, 0.f);
            size_t obase = ((size_t)(b0 + b)*T + t)*H + hu0 + 2*u2;
            *(float2*)&out[obase] = outv;

            if (t == T - 1) {
                size_t hoff = (size_t)B*T*H + (size_t)(b0 + b)*H + hu0 + 2*u2;
                *(float2*)&out[hoff] = make_float2(hca, hcb);
                *(float2*)&out[hoff + (size_t)B*H] = creg;
            }
        }

        // ---- Grid barrier (all 128 blocks co-resident by construction) ----
        if (t + 1 < T) {
            __syncthreads();
            if (tid == 0) {
                __threadfence();
                atomicAdd(&g_bar, 1u);
                unsigned target = (unsigned)NBLK * (unsigned)(t + 1);
                while (*((volatile unsigned*)&g_bar) < target) { }
                __threadfence();
            }
            __syncthreads();
        }
    }
}

extern "C" void kernel_launch(void* const* d_in, const int* in_sizes, int n_in,
                              void* d_out, int out_size) {
    const int*   x     = (const int*)d_in[0];
    const int*   x_len = (const int*)d_in[1];
    const float* W_ih  = (const float*)d_in[2];
    const float* W_hh  = (const float*)d_in[3];
    const float* b_ih  = (const float*)d_in[4];
    const float* b_hh  = (const float*)d_in[5];
    float* out = (float*)d_out;

    cudaFuncSetAttribute(lstm_persistent,
                         cudaFuncAttributeMaxDynamicSharedMemorySize, SMEM_BYTES);

    init_kernel<<<256, 256>>>(W_ih, b_ih, b_hh);
    lstm_persistent<<<NBLK, NTHR, SMEM_BYTES>>>(x, x_len, W_hh, out);
}